// round 12
// baseline (speedup 1.0000x reference)
#include <cuda_runtime.h>
#include <cuda_bf16.h>
#include <cstdint>

// Batched exp of log-affine matrices (ndims=3), B=1e6.
// R12: warp-private persistent pipelines. Each of the 4 warps in a CTA owns
// an independent 3-stage ring (64 matrices / 3 KB per stage), with its own
// mbarriers and lane-0-issued cp.async.bulk load/store. NO __syncthreads
// anywhere -> no CTA-wide convoy (R11's residual serializer: shared chunk
// barrier + syncthreads + warp0-serial refill).
// Math: packed f32x2, two matrices/thread, s=1 scaling, deg-4 Taylor
// (Paterson-Stockmeyer), deg-3 phi1 chain, one affine squaring.
// rel_err ~4e-6 << 1e-3 bar (measured R9-R11).

#define TPB 128
#define NWARP 4
#define CHUNKW 64            // matrices per warp-chunk (2 per lane)
#define NSTAGE 3
#define NSM 148
#define CTAS_PER_SM 6

typedef unsigned long long u64;

__device__ __forceinline__ uint32_t smem_u32(const void* p) {
    return (uint32_t)__cvta_generic_to_shared(p);
}

__device__ __forceinline__ u64 pk(float lo, float hi) {
    u64 r;
    asm("mov.b64 %0, {%1, %2};" : "=l"(r) : "f"(lo), "f"(hi));
    return r;
}
__device__ __forceinline__ void upk(u64 v, float& lo, float& hi) {
    asm("mov.b64 {%0, %1}, %2;" : "=f"(lo), "=f"(hi) : "l"(v));
}
__device__ __forceinline__ u64 ffma2(u64 a, u64 b, u64 c) {
    u64 d;
    asm("fma.rn.f32x2 %0, %1, %2, %3;" : "=l"(d) : "l"(a), "l"(b), "l"(c));
    return d;
}
__device__ __forceinline__ u64 fmul2(u64 a, u64 b) {
    u64 d;
    asm("mul.rn.f32x2 %0, %1, %2;" : "=l"(d) : "l"(a), "l"(b));
    return d;
}
__device__ __forceinline__ u64 fadd2(u64 a, u64 b) {
    u64 d;
    asm("add.rn.f32x2 %0, %1, %2;" : "=l"(d) : "l"(a), "l"(b));
    return d;
}

__device__ __forceinline__ void mm33p(const u64* __restrict__ X,
                                      const u64* __restrict__ Y,
                                      u64* __restrict__ Z) {
#pragma unroll
    for (int r = 0; r < 3; r++) {
        const u64 x0 = X[r * 3 + 0], x1 = X[r * 3 + 1], x2 = X[r * 3 + 2];
#pragma unroll
        for (int c = 0; c < 3; c++)
            Z[r * 3 + c] = ffma2(x0, Y[c], ffma2(x1, Y[3 + c], fmul2(x2, Y[6 + c])));
    }
}

__device__ __forceinline__ void mv3p(const u64* __restrict__ X,
                                     const u64* __restrict__ v,
                                     u64* __restrict__ w) {
#pragma unroll
    for (int r = 0; r < 3; r++)
        w[r] = ffma2(X[r * 3 + 0], v[0],
               ffma2(X[r * 3 + 1], v[1], fmul2(X[r * 3 + 2], v[2])));
}

// Compute one warp-chunk in place. buf = warp's stage buffer (CHUNKW*3 float4).
__device__ __forceinline__ void process_wchunk(float4* __restrict__ buf,
                                               int lane, int nblk) {
    const bool full = (nblk == CHUNKW);
    const int ia = lane;
    const int ib = 32 + lane;

    float4 a0, a1, a2, b0, b1, b2;
    if (full) {
        a0 = buf[3 * ia + 0]; a1 = buf[3 * ia + 1]; a2 = buf[3 * ia + 2];
        b0 = buf[3 * ib + 0]; b1 = buf[3 * ib + 1]; b2 = buf[3 * ib + 2];
    } else {
        float4 z = make_float4(0.f, 0.f, 0.f, 0.f);
        a0 = a1 = a2 = b0 = b1 = b2 = z;
        if (ia < nblk) { a0 = buf[3 * ia + 0]; a1 = buf[3 * ia + 1]; a2 = buf[3 * ia + 2]; }
        if (ib < nblk) { b0 = buf[3 * ib + 0]; b1 = buf[3 * ib + 1]; b2 = buf[3 * ib + 2]; }
    }

    u64 A[9] = {pk(a0.x, b0.x), pk(a0.y, b0.y), pk(a0.z, b0.z),
                pk(a1.x, b1.x), pk(a1.y, b1.y), pk(a1.z, b1.z),
                pk(a2.x, b2.x), pk(a2.y, b2.y), pk(a2.z, b2.z)};
    u64 t[3] = {pk(a0.w, b0.w), pk(a1.w, b1.w), pk(a2.w, b2.w)};

    // S = 2^-1 folded coefficients
    const float f1 = 0.5f;           // S
    const float f2 = 0.125f;         // S^2/2
    const float f3 = 1.0f / 48.0f;   // S^3/6
    const float f4 = 1.0f / 384.0f;  // S^4/24
    const u64 c1 = pk(f1, f1), c2 = pk(f2, f2);
    const u64 c3 = pk(f3, f3), c4 = pk(f4, f4);
    const u64 one = pk(1.0f, 1.0f);

    // phi1 chain (deg-3): u = c1*t + c2*A t + c3*A^2 t
    u64 w1[3], w2[3], u[3];
    mv3p(A, t, w1);
    mv3p(A, w1, w2);
#pragma unroll
    for (int j = 0; j < 3; j++)
        u[j] = ffma2(t[j], c1, ffma2(w1[j], c2, fmul2(w2[j], c3)));

    // B = A^2
    u64 B[9];
    mm33p(A, A, B);

    // C = c3*A + c4*B  (B*C = S^3 A^3/6 + S^4 A^4/24)
    u64 C[9];
#pragma unroll
    for (int j = 0; j < 9; j++) C[j] = ffma2(B[j], c4, fmul2(A[j], c3));

    // E = I + c1*A + c2*B + B*C, row-wise
    u64 E[9];
#pragma unroll
    for (int r = 0; r < 3; r++) {
        const u64 b0r = B[r * 3 + 0], b1r = B[r * 3 + 1], b2r = B[r * 3 + 2];
#pragma unroll
        for (int c = 0; c < 3; c++) {
            u64 g = ffma2(b0r, C[c], ffma2(b1r, C[3 + c], fmul2(b2r, C[6 + c])));
            u64 e = ffma2(A[r * 3 + c], c1, ffma2(B[r * 3 + c], c2, g));
            if (c == r) e = fadd2(e, one);
            E[r * 3 + c] = e;
        }
    }

    // One affine squaring: [E,u] -> [E^2, E u + u]
    u64 F[9], v2[3];
    mm33p(E, E, F);
    mv3p(E, u, v2);
#pragma unroll
    for (int j = 0; j < 3; j++) u[j] = fadd2(v2[j], u[j]);

    float ea[12], eb[12];
    upk(F[0], ea[0], eb[0]);   upk(F[1], ea[1], eb[1]);   upk(F[2], ea[2], eb[2]);
    upk(u[0], ea[3], eb[3]);
    upk(F[3], ea[4], eb[4]);   upk(F[4], ea[5], eb[5]);   upk(F[5], ea[6], eb[6]);
    upk(u[1], ea[7], eb[7]);
    upk(F[6], ea[8], eb[8]);   upk(F[7], ea[9], eb[9]);   upk(F[8], ea[10], eb[10]);
    upk(u[2], ea[11], eb[11]);

    if (full || ia < nblk) {
        buf[3 * ia + 0] = make_float4(ea[0], ea[1], ea[2], ea[3]);
        buf[3 * ia + 1] = make_float4(ea[4], ea[5], ea[6], ea[7]);
        buf[3 * ia + 2] = make_float4(ea[8], ea[9], ea[10], ea[11]);
    }
    if (full || ib < nblk) {
        buf[3 * ib + 0] = make_float4(eb[0], eb[1], eb[2], eb[3]);
        buf[3 * ib + 1] = make_float4(eb[4], eb[5], eb[6], eb[7]);
        buf[3 * ib + 2] = make_float4(eb[8], eb[9], eb[10], eb[11]);
    }
}

__device__ __forceinline__ void mbar_wait(uint32_t mbar_a, uint32_t parity) {
    uint32_t done;
    asm volatile(
        "{\n\t.reg .pred p;\n\t"
        "mbarrier.try_wait.parity.acquire.cta.shared::cta.b64 p, [%1], %2;\n\t"
        "selp.b32 %0, 1, 0, p;\n\t}"
        : "=r"(done) : "r"(mbar_a), "r"(parity) : "memory");
    if (!done) {
        asm volatile(
            "{\n\t.reg .pred P1;\n\t"
            "WL_%=:\n\t"
            "mbarrier.try_wait.parity.acquire.cta.shared::cta.b64 P1, [%0], %1, 0x989680;\n\t"
            "@P1 bra.uni WD_%=;\n\t"
            "bra.uni WL_%=;\n\t"
            "WD_%=:\n\t}"
            :: "r"(mbar_a), "r"(parity) : "memory");
    }
}

__global__ void __launch_bounds__(TPB)
expaff_kernel(const float4* __restrict__ in, float4* __restrict__ out,
              int n, int nwch) {
    // Per-warp, per-stage buffers: [warp][stage][CHUNKW*3] float4 = 36 KB.
    __shared__ alignas(16) float4 buf[NWARP][NSTAGE][CHUNKW * 3];
    __shared__ alignas(8) unsigned long long mbar[NWARP][NSTAGE];

    const int tid = threadIdx.x;
    const int wid = tid >> 5;
    const int lane = tid & 31;
    const int gwid = blockIdx.x * NWARP + wid;   // global warp-pipeline id
    const int GW = gridDim.x * NWARP;

    // Each warp initializes its own barriers; warp-scope sync only.
    if (lane == 0) {
#pragma unroll
        for (int s = 0; s < NSTAGE; s++)
            asm volatile("mbarrier.init.shared.b64 [%0], 1;"
                         :: "r"(smem_u32(&mbar[wid][s])) : "memory");
    }
    __syncwarp();

    // Prologue: fill this warp's ring.
    if (lane == 0) {
#pragma unroll
        for (int k = 0; k < NSTAGE; k++) {
            int c = gwid + k * GW;
            if (c < nwch) {
                int cbase = c * CHUNKW;
                int nb = min(CHUNKW, n - cbase);
                uint32_t bytes = (uint32_t)nb * 48u;
                uint32_t mb = smem_u32(&mbar[wid][k]);
                asm volatile("mbarrier.arrive.expect_tx.shared.b64 _, [%0], %1;"
                             :: "r"(mb), "r"(bytes) : "memory");
                asm volatile(
                    "cp.async.bulk.shared::cta.global.mbarrier::complete_tx::bytes "
                    "[%0], [%1], %2, [%3];"
                    :: "r"(smem_u32(&buf[wid][k][0])), "l"(in + (size_t)cbase * 3),
                       "r"(bytes), "r"(mb)
                    : "memory");
            }
        }
    }

    // Warp-independent main loop.
    for (int j = 0, c = gwid; c < nwch; j++, c += GW) {
        const int s = j % NSTAGE;
        const uint32_t parity = (uint32_t)((j / NSTAGE) & 1);
        const int cbase = c * CHUNKW;
        const int nb = min(CHUNKW, n - cbase);
        const uint32_t bytes = (uint32_t)nb * 48u;
        const uint32_t mb = smem_u32(&mbar[wid][s]);

        mbar_wait(mb, parity);

        process_wchunk(&buf[wid][s][0], lane, nb);

        // Order this lane's smem writes before the async-proxy TMA read,
        // then make sure every lane has done so.
        asm volatile("fence.proxy.async.shared::cta;" ::: "memory");
        __syncwarp();

        if (lane == 0) {
            asm volatile(
                "cp.async.bulk.global.shared::cta.bulk_group [%0], [%1], %2;"
                :: "l"(out + (size_t)cbase * 3), "r"(smem_u32(&buf[wid][s][0])),
                   "r"(bytes)
                : "memory");
            asm volatile("cp.async.bulk.commit_group;" ::: "memory");

            // Refill this stage with chunk c + NSTAGE*GW, if any.
            int cn = c + NSTAGE * GW;
            if (cn < nwch) {
                // Bulk-async groups are per-thread (lane 0): wait until all
                // outstanding stores finished READING smem before reuse.
                asm volatile("cp.async.bulk.wait_group.read 0;" ::: "memory");
                int cnbase = cn * CHUNKW;
                int nb2 = min(CHUNKW, n - cnbase);
                uint32_t bytes2 = (uint32_t)nb2 * 48u;
                asm volatile("mbarrier.arrive.expect_tx.shared.b64 _, [%0], %1;"
                             :: "r"(mb), "r"(bytes2) : "memory");
                asm volatile(
                    "cp.async.bulk.shared::cta.global.mbarrier::complete_tx::bytes "
                    "[%0], [%1], %2, [%3];"
                    :: "r"(smem_u32(&buf[wid][s][0])), "l"(in + (size_t)cnbase * 3),
                       "r"(bytes2), "r"(mb)
                    : "memory");
            }
        }
    }

    // smem must stay valid until this warp's stores complete.
    if (lane == 0) {
        asm volatile("cp.async.bulk.wait_group 0;" ::: "memory");
    }
}

extern "C" void kernel_launch(void* const* d_in, const int* in_sizes, int n_in,
                              void* d_out, int out_size) {
    const float* vec = (const float*)d_in[0];
    float* outp = (float*)d_out;
    int n = in_sizes[0] / 12;
    int nwch = (n + CHUNKW - 1) / CHUNKW;

    int grid = NSM * CTAS_PER_SM;
    int maxg = (nwch + NWARP - 1) / NWARP;
    if (grid > maxg) grid = maxg;
    expaff_kernel<<<grid, TPB>>>((const float4*)vec, (float4*)outp, n, nwch);
}